// round 1
// baseline (speedup 1.0000x reference)
#include <cuda_runtime.h>
#include <cstdint>

// Flash attention, tf32 mma.sync (m16n8k8), fp32 accumulate.
// B=16, Q=2048, K=2048, D=128. Per-batch key masking via valid_lens:
// masked score = -1e6 -> weight underflows to 0, so tiles fully past
// valid_len are skipped entirely.

static constexpr int BQ   = 128;   // query rows per CTA
static constexpr int BKT  = 64;    // keys per tile
static constexpr int HD   = 128;   // head dim
static constexpr int SEQ  = 2048;
static constexpr int KSTR = 136;   // smem row stride (mod 32 = 8 banks -> conflict-free frags)
static constexpr int PSTR = 68;    // P smem stride (mod 32 = 4 -> conflict-free A reads)

__device__ __forceinline__ unsigned f2tf(float x) {
    unsigned r;
    asm("cvt.rna.tf32.f32 %0, %1;" : "=r"(r) : "f"(x));
    return r;
}

__device__ __forceinline__ void mma8(float* c,
                                     unsigned a0, unsigned a1, unsigned a2, unsigned a3,
                                     unsigned b0, unsigned b1) {
    asm volatile(
        "mma.sync.aligned.m16n8k8.row.col.f32.tf32.tf32.f32 "
        "{%0,%1,%2,%3}, {%4,%5,%6,%7}, {%8,%9}, {%0,%1,%2,%3};\n"
        : "+f"(c[0]), "+f"(c[1]), "+f"(c[2]), "+f"(c[3])
        : "r"(a0), "r"(a1), "r"(a2), "r"(a3), "r"(b0), "r"(b1));
}

extern __shared__ float smem[];

__global__ __launch_bounds__(256, 1)
void fa_tf32_kernel(const float* __restrict__ q,
                    const float* __restrict__ k,
                    const float* __restrict__ v,
                    const int*   __restrict__ vlens,
                    float*       __restrict__ out) {
    float* sQ = smem;                    // 128 x 136
    float* sK = sQ + BQ * KSTR;          // 64 x 136
    float* sV = sK + BKT * KSTR;         // 64 x 136
    float* sP = sV + BKT * KSTR;         // 8 warps x 16 x 68

    const int tid  = threadIdx.x;
    const int warp = tid >> 5;
    const int lane = tid & 31;
    const int g    = lane >> 2;          // groupID
    const int t    = lane & 3;           // thread-in-group
    const int b    = blockIdx.y;
    const int q0   = blockIdx.x * BQ;

    const int vlen = vlens[b];
    const int nkt  = (vlen + BKT - 1) >> 6;

    const float scale = 0.088388347648318447f;  // 1/sqrt(128)

    // ---- Load Q tile: scale + tf32-round into smem ----
    {
        const float4* gQ = reinterpret_cast<const float4*>(q + ((size_t)b * SEQ + q0) * HD);
        #pragma unroll
        for (int i = 0; i < 16; i++) {
            int idx = tid + i * 256;           // 0..4095 float4s
            int row = idx >> 5;
            int c4  = idx & 31;
            float4 val = gQ[idx];
            float4 o;
            o.x = __uint_as_float(f2tf(val.x * scale));
            o.y = __uint_as_float(f2tf(val.y * scale));
            o.z = __uint_as_float(f2tf(val.z * scale));
            o.w = __uint_as_float(f2tf(val.w * scale));
            *reinterpret_cast<float4*>(&sQ[row * KSTR + c4 * 4]) = o;
        }
    }

    const int wrow = warp * 16;
    float* sPw = sP + warp * 16 * PSTR;

    float m0 = -1e30f, m1 = -1e30f;
    float l0 = 0.f,    l1 = 0.f;
    float oAcc[16][4];
    #pragma unroll
    for (int n = 0; n < 16; n++)
        #pragma unroll
        for (int e = 0; e < 4; e++) oAcc[n][e] = 0.f;

    for (int kt = 0; kt < nkt; kt++) {
        const int kbase = kt * BKT;
        if (kt > 0) __syncthreads();   // all warps done reading previous K/V

        // ---- Load K,V tile (tf32-round into smem) ----
        {
            const float4* gK = reinterpret_cast<const float4*>(k + ((size_t)b * SEQ + kbase) * HD);
            const float4* gV = reinterpret_cast<const float4*>(v + ((size_t)b * SEQ + kbase) * HD);
            #pragma unroll
            for (int i = 0; i < 8; i++) {
                int idx = tid + i * 256;       // 0..2047 float4s
                int row = idx >> 5;
                int c4  = idx & 31;
                float4 kk = gK[idx];
                float4 ok;
                ok.x = __uint_as_float(f2tf(kk.x));
                ok.y = __uint_as_float(f2tf(kk.y));
                ok.z = __uint_as_float(f2tf(kk.z));
                ok.w = __uint_as_float(f2tf(kk.w));
                *reinterpret_cast<float4*>(&sK[row * KSTR + c4 * 4]) = ok;
                float4 vv = gV[idx];
                float4 ov;
                ov.x = __uint_as_float(f2tf(vv.x));
                ov.y = __uint_as_float(f2tf(vv.y));
                ov.z = __uint_as_float(f2tf(vv.z));
                ov.w = __uint_as_float(f2tf(vv.w));
                *reinterpret_cast<float4*>(&sV[row * KSTR + c4 * 4]) = ov;
            }
        }
        __syncthreads();

        // ---- S = (Q*scale) @ K^T  (16 x 64 per warp) ----
        float sAcc[8][4];
        #pragma unroll
        for (int n = 0; n < 8; n++)
            #pragma unroll
            for (int e = 0; e < 4; e++) sAcc[n][e] = 0.f;

        #pragma unroll
        for (int s = 0; s < 16; s++) {
            unsigned a0 = __float_as_uint(sQ[(wrow + g) * KSTR + s * 8 + t]);
            unsigned a1 = __float_as_uint(sQ[(wrow + g + 8) * KSTR + s * 8 + t]);
            unsigned a2 = __float_as_uint(sQ[(wrow + g) * KSTR + s * 8 + t + 4]);
            unsigned a3 = __float_as_uint(sQ[(wrow + g + 8) * KSTR + s * 8 + t + 4]);
            #pragma unroll
            for (int n = 0; n < 8; n++) {
                unsigned b0 = __float_as_uint(sK[(n * 8 + g) * KSTR + s * 8 + t]);
                unsigned b1 = __float_as_uint(sK[(n * 8 + g) * KSTR + s * 8 + t + 4]);
                mma8(sAcc[n], a0, a1, a2, a3, b0, b1);
            }
        }

        // ---- Mask boundary tile ----
        if (kbase + BKT > vlen) {
            #pragma unroll
            for (int n = 0; n < 8; n++) {
                int key = kbase + n * 8 + 2 * t;
                if (key     >= vlen) { sAcc[n][0] = -1e6f; sAcc[n][2] = -1e6f; }
                if (key + 1 >= vlen) { sAcc[n][1] = -1e6f; sAcc[n][3] = -1e6f; }
            }
        }

        // ---- Online softmax ----
        float tm0 = -1e30f, tm1 = -1e30f;
        #pragma unroll
        for (int n = 0; n < 8; n++) {
            tm0 = fmaxf(tm0, fmaxf(sAcc[n][0], sAcc[n][1]));
            tm1 = fmaxf(tm1, fmaxf(sAcc[n][2], sAcc[n][3]));
        }
        tm0 = fmaxf(tm0, __shfl_xor_sync(0xffffffffu, tm0, 1));
        tm0 = fmaxf(tm0, __shfl_xor_sync(0xffffffffu, tm0, 2));
        tm1 = fmaxf(tm1, __shfl_xor_sync(0xffffffffu, tm1, 1));
        tm1 = fmaxf(tm1, __shfl_xor_sync(0xffffffffu, tm1, 2));

        float nm0 = fmaxf(m0, tm0), nm1 = fmaxf(m1, tm1);
        float alpha0 = __expf(m0 - nm0), alpha1 = __expf(m1 - nm1);
        m0 = nm0; m1 = nm1;

        float rs0 = 0.f, rs1 = 0.f;
        #pragma unroll
        for (int n = 0; n < 8; n++) {
            float p0 = __expf(sAcc[n][0] - nm0);
            float p1 = __expf(sAcc[n][1] - nm0);
            float p2 = __expf(sAcc[n][2] - nm1);
            float p3 = __expf(sAcc[n][3] - nm1);
            rs0 += p0 + p1;
            rs1 += p2 + p3;
            *reinterpret_cast<float2*>(&sPw[g * PSTR + n * 8 + 2 * t])       = make_float2(p0, p1);
            *reinterpret_cast<float2*>(&sPw[(g + 8) * PSTR + n * 8 + 2 * t]) = make_float2(p2, p3);
        }
        rs0 += __shfl_xor_sync(0xffffffffu, rs0, 1);
        rs0 += __shfl_xor_sync(0xffffffffu, rs0, 2);
        rs1 += __shfl_xor_sync(0xffffffffu, rs1, 1);
        rs1 += __shfl_xor_sync(0xffffffffu, rs1, 2);
        l0 = l0 * alpha0 + rs0;
        l1 = l1 * alpha1 + rs1;

        #pragma unroll
        for (int n = 0; n < 16; n++) {
            oAcc[n][0] *= alpha0; oAcc[n][1] *= alpha0;
            oAcc[n][2] *= alpha1; oAcc[n][3] *= alpha1;
        }

        __syncwarp();

        // ---- O += P @ V  (16 x 128 per warp) ----
        #pragma unroll
        for (int s = 0; s < 8; s++) {
            unsigned a0 = __float_as_uint(sPw[g * PSTR + s * 8 + t]);
            unsigned a1 = __float_as_uint(sPw[(g + 8) * PSTR + s * 8 + t]);
            unsigned a2 = __float_as_uint(sPw[g * PSTR + s * 8 + t + 4]);
            unsigned a3 = __float_as_uint(sPw[(g + 8) * PSTR + s * 8 + t + 4]);
            #pragma unroll
            for (int n = 0; n < 16; n++) {
                unsigned b0 = __float_as_uint(sV[(s * 8 + t) * KSTR + n * 8 + g]);
                unsigned b1 = __float_as_uint(sV[(s * 8 + t + 4) * KSTR + n * 8 + g]);
                mma8(oAcc[n], a0, a1, a2, a3, b0, b1);
            }
        }
    }

    // ---- Finalize: normalize and write out ----
    float inv0 = 1.f / l0;
    float inv1 = 1.f / l1;
    float* gO = out + ((size_t)b * SEQ + q0 + wrow) * HD;
    #pragma unroll
    for (int n = 0; n < 16; n++) {
        *reinterpret_cast<float2*>(&gO[g * HD + n * 8 + 2 * t]) =
            make_float2(oAcc[n][0] * inv0, oAcc[n][1] * inv0);
        *reinterpret_cast<float2*>(&gO[(g + 8) * HD + n * 8 + 2 * t]) =
            make_float2(oAcc[n][2] * inv1, oAcc[n][3] * inv1);
    }
}

extern "C" void kernel_launch(void* const* d_in, const int* in_sizes, int n_in,
                              void* d_out, int out_size) {
    const float* q  = (const float*)d_in[0];
    const float* k  = (const float*)d_in[1];
    const float* v  = (const float*)d_in[2];
    const int*   vl = (const int*)d_in[3];
    float* out = (float*)d_out;

    size_t smem_bytes = (size_t)(BQ * KSTR + 2 * BKT * KSTR + 8 * 16 * PSTR) * sizeof(float); // 174080
    cudaFuncSetAttribute(fa_tf32_kernel, cudaFuncAttributeMaxDynamicSharedMemorySize, (int)smem_bytes);

    dim3 grid(SEQ / BQ, 16);  // (16, 16)
    fa_tf32_kernel<<<grid, 256, smem_bytes>>>(q, k, v, vl, out);
}

// round 3
// speedup vs baseline: 1.6328x; 1.6328x over previous
#include <cuda_runtime.h>
#include <cstdint>

// Flash attention, tf32 mma.sync (m16n8k8), fp32 accumulate.
// B=16, Q=2048, K=2048, D=128. Per-batch key masking via valid_lens.
// Round 3: fix cp.async byte addressing (float4 index * 16 bytes).
// Stride-128 XOR swizzles (conflict-free fragment LDS),
// cp.async double-buffered K/V with in-register tf32 conversion.

static constexpr int BQ   = 128;
static constexpr int BKT  = 64;
static constexpr int HD   = 128;
static constexpr int SEQ  = 2048;
static constexpr int PSTR = 68;

// smem float offsets
static constexpr int Q_OFF  = 0;                 // 128*128 = 16384
static constexpr int KV_OFF = 16384;             // 2 buffers * (K 8192 | V 8192) = 32768
static constexpr int P_OFF  = 16384 + 32768;     // 8*16*68 = 8704
static constexpr int SMEM_FLOATS = P_OFF + 8 * 16 * PSTR;   // 57856 -> 231424 B

__device__ __forceinline__ unsigned f2tf(float x) {
    unsigned r;
    asm("cvt.rna.tf32.f32 %0, %1;" : "=r"(r) : "f"(x));
    return r;
}

__device__ __forceinline__ void mma8(float* c,
                                     unsigned a0, unsigned a1, unsigned a2, unsigned a3,
                                     unsigned b0, unsigned b1) {
    asm volatile(
        "mma.sync.aligned.m16n8k8.row.col.f32.tf32.tf32.f32 "
        "{%0,%1,%2,%3}, {%4,%5,%6,%7}, {%8,%9}, {%0,%1,%2,%3};\n"
        : "+f"(c[0]), "+f"(c[1]), "+f"(c[2]), "+f"(c[3])
        : "r"(a0), "r"(a1), "r"(a2), "r"(a3), "r"(b0), "r"(b1));
}

__device__ __forceinline__ void cpa16(uint32_t dst, const void* src) {
    asm volatile("cp.async.cg.shared.global [%0], [%1], 16;\n" :: "r"(dst), "l"(src));
}

extern __shared__ float smem[];

__global__ __launch_bounds__(256, 1)
void fa_tf32_kernel(const float* __restrict__ q,
                    const float* __restrict__ k,
                    const float* __restrict__ v,
                    const int*   __restrict__ vlens,
                    float*       __restrict__ out) {
    const int tid  = threadIdx.x;
    const int warp = tid >> 5;
    const int lane = tid & 31;
    const int g    = lane >> 2;
    const int t    = lane & 3;
    const int b    = blockIdx.y;
    const int q0   = blockIdx.x * BQ;

    const int vlen = vlens[b];
    const int nkt  = (vlen + BKT - 1) >> 6;

    const float scale = 0.088388347648318447f;  // 1/sqrt(128)

    uint32_t smem_u32;
    asm("{ .reg .u64 tmp; cvta.to.shared.u64 tmp, %1; cvt.u32.u64 %0, tmp; }"
        : "=r"(smem_u32) : "l"(smem));

    // byte bases for cp.async destinations
    const uint32_t kvK_base = smem_u32 + (uint32_t)KV_OFF * 4u;            // K buf0
    const uint32_t kvV_base = kvK_base + 8192u * 4u;                       // V buf0

    const float4* gK4 = reinterpret_cast<const float4*>(k + (size_t)b * SEQ * HD);
    const float4* gV4 = reinterpret_cast<const float4*>(v + (size_t)b * SEQ * HD);

    // ---- Issue cp.async for K/V tile 0 into buffer 0 ----
    {
        #pragma unroll
        for (int i = 0; i < 8; i++) {
            int idx = tid + i * 256;       // 0..2047 float4s
            int row = idx >> 5;            // key row 0..63
            int c4  = idx & 31;
            int dK = row * 32 + (c4 ^ (row & 7));          // K swizzle (float4 idx)
            int dV = row * 32 + (c4 ^ ((row & 7) << 1));   // V swizzle (float4 idx)
            cpa16(kvK_base + (uint32_t)dK * 16u, gK4 + idx);
            cpa16(kvV_base + (uint32_t)dV * 16u, gV4 + idx);
        }
        asm volatile("cp.async.commit_group;\n" ::: "memory");
    }

    // ---- Load Q tile: scale + tf32-round into swizzled smem ----
    {
        float* sQ = smem + Q_OFF;
        const float4* gQ = reinterpret_cast<const float4*>(q + ((size_t)b * SEQ + q0) * HD);
        #pragma unroll
        for (int i = 0; i < 16; i++) {
            int idx = tid + i * 256;       // 0..4095 float4s
            int row = idx >> 5;
            int c4  = idx & 31;
            float4 val = gQ[idx];
            float4 o;
            o.x = __uint_as_float(f2tf(val.x * scale));
            o.y = __uint_as_float(f2tf(val.y * scale));
            o.z = __uint_as_float(f2tf(val.z * scale));
            o.w = __uint_as_float(f2tf(val.w * scale));
            int d4 = row * 32 + (c4 ^ (row & 7));          // Q swizzle (same as K)
            *reinterpret_cast<float4*>(&sQ[d4 * 4]) = o;
        }
    }

    const int wrow = warp * 16;
    const float* sQ = smem + Q_OFF;
    float* sPw = smem + P_OFF + warp * 16 * PSTR;

    float m0 = -1e30f, m1 = -1e30f;
    float l0 = 0.f,    l1 = 0.f;
    float oAcc[16][4];
    #pragma unroll
    for (int n = 0; n < 16; n++)
        #pragma unroll
        for (int e = 0; e < 4; e++) oAcc[n][e] = 0.f;

    for (int kt = 0; kt < nkt; kt++) {
        const int kbase = kt * BKT;

        // ---- Issue next tile's cp.async into the alternate buffer ----
        if (kt + 1 < nkt) {
            uint32_t nb = (uint32_t)((kt + 1) & 1) * 16384u * 4u;   // byte offset of buffer
            int koff = (kt + 1) * BKT * 32;   // float4 offset into gK4/gV4
            #pragma unroll
            for (int i = 0; i < 8; i++) {
                int idx = tid + i * 256;
                int row = idx >> 5;
                int c4  = idx & 31;
                int dK = row * 32 + (c4 ^ (row & 7));
                int dV = row * 32 + (c4 ^ ((row & 7) << 1));
                cpa16(kvK_base + nb + (uint32_t)dK * 16u, gK4 + koff + idx);
                cpa16(kvV_base + nb + (uint32_t)dV * 16u, gV4 + koff + idx);
            }
            asm volatile("cp.async.commit_group;\n" ::: "memory");
            asm volatile("cp.async.wait_group 1;\n" ::: "memory");
        } else {
            asm volatile("cp.async.wait_group 0;\n" ::: "memory");
        }
        __syncthreads();

        const float* sK = smem + KV_OFF + (kt & 1) * 16384;
        const float* sV = sK + 8192;

        // ---- S = (Q*scale) @ K^T  (16 x 64 per warp) ----
        float sAcc[8][4];
        #pragma unroll
        for (int n = 0; n < 8; n++)
            #pragma unroll
            for (int e = 0; e < 4; e++) sAcc[n][e] = 0.f;

        #pragma unroll
        for (int s = 0; s < 16; s++) {
            const int cA0 = ((2 * s)     ^ g) * 4 + t;   // col4=2s   swizzled
            const int cA1 = ((2 * s + 1) ^ g) * 4 + t;   // col4=2s+1
            unsigned a0 = __float_as_uint(sQ[(wrow + g) * 128     + cA0]);
            unsigned a1 = __float_as_uint(sQ[(wrow + g + 8) * 128 + cA0]);
            unsigned a2 = __float_as_uint(sQ[(wrow + g) * 128     + cA1]);
            unsigned a3 = __float_as_uint(sQ[(wrow + g + 8) * 128 + cA1]);
            #pragma unroll
            for (int n = 0; n < 8; n++) {
                unsigned b0 = f2tf(sK[(n * 8 + g) * 128 + cA0]);
                unsigned b1 = f2tf(sK[(n * 8 + g) * 128 + cA1]);
                mma8(sAcc[n], a0, a1, a2, a3, b0, b1);
            }
        }

        // ---- Mask boundary tile ----
        if (kbase + BKT > vlen) {
            #pragma unroll
            for (int n = 0; n < 8; n++) {
                int key = kbase + n * 8 + 2 * t;
                if (key     >= vlen) { sAcc[n][0] = -1e6f; sAcc[n][2] = -1e6f; }
                if (key + 1 >= vlen) { sAcc[n][1] = -1e6f; sAcc[n][3] = -1e6f; }
            }
        }

        // ---- Online softmax ----
        float tm0 = -1e30f, tm1 = -1e30f;
        #pragma unroll
        for (int n = 0; n < 8; n++) {
            tm0 = fmaxf(tm0, fmaxf(sAcc[n][0], sAcc[n][1]));
            tm1 = fmaxf(tm1, fmaxf(sAcc[n][2], sAcc[n][3]));
        }
        tm0 = fmaxf(tm0, __shfl_xor_sync(0xffffffffu, tm0, 1));
        tm0 = fmaxf(tm0, __shfl_xor_sync(0xffffffffu, tm0, 2));
        tm1 = fmaxf(tm1, __shfl_xor_sync(0xffffffffu, tm1, 1));
        tm1 = fmaxf(tm1, __shfl_xor_sync(0xffffffffu, tm1, 2));

        float nm0 = fmaxf(m0, tm0), nm1 = fmaxf(m1, tm1);
        float alpha0 = __expf(m0 - nm0), alpha1 = __expf(m1 - nm1);
        m0 = nm0; m1 = nm1;

        float rs0 = 0.f, rs1 = 0.f;
        #pragma unroll
        for (int n = 0; n < 8; n++) {
            float p0 = __expf(sAcc[n][0] - nm0);
            float p1 = __expf(sAcc[n][1] - nm0);
            float p2 = __expf(sAcc[n][2] - nm1);
            float p3 = __expf(sAcc[n][3] - nm1);
            rs0 += p0 + p1;
            rs1 += p2 + p3;
            *reinterpret_cast<float2*>(&sPw[g * PSTR + n * 8 + 2 * t])       = make_float2(p0, p1);
            *reinterpret_cast<float2*>(&sPw[(g + 8) * PSTR + n * 8 + 2 * t]) = make_float2(p2, p3);
        }
        rs0 += __shfl_xor_sync(0xffffffffu, rs0, 1);
        rs0 += __shfl_xor_sync(0xffffffffu, rs0, 2);
        rs1 += __shfl_xor_sync(0xffffffffu, rs1, 1);
        rs1 += __shfl_xor_sync(0xffffffffu, rs1, 2);
        l0 = l0 * alpha0 + rs0;
        l1 = l1 * alpha1 + rs1;

        #pragma unroll
        for (int n = 0; n < 16; n++) {
            oAcc[n][0] *= alpha0; oAcc[n][1] *= alpha0;
            oAcc[n][2] *= alpha1; oAcc[n][3] *= alpha1;
        }

        __syncwarp();

        // ---- O += P @ V  (16 x 128 per warp) ----
        #pragma unroll
        for (int s = 0; s < 8; s++) {
            unsigned a0 = __float_as_uint(sPw[g * PSTR + s * 8 + t]);
            unsigned a1 = __float_as_uint(sPw[(g + 8) * PSTR + s * 8 + t]);
            unsigned a2 = __float_as_uint(sPw[g * PSTR + s * 8 + t + 4]);
            unsigned a3 = __float_as_uint(sPw[(g + 8) * PSTR + s * 8 + t + 4]);
            const int r0 = (s * 8 + t) * 128;
            const int r1 = (s * 8 + t + 4) * 128;
            const int u  = g >> 2;
            const int w  = g & 3;
            #pragma unroll
            for (int n = 0; n < 16; n++) {
                // b0: row s*8+t   (row&7 == t),   swizzle XOR 2t
                // b1: row s*8+t+4 (row&7 == t+4), swizzle XOR 2t+8
                unsigned b0 = f2tf(sV[r0 + ((2 * n + u) ^ (2 * t)) * 4 + w]);
                unsigned b1 = f2tf(sV[r1 + ((2 * n + u) ^ (2 * t + 8)) * 4 + w]);
                mma8(oAcc[n], a0, a1, a2, a3, b0, b1);
            }
        }

        __syncthreads();   // protect this tile's buffer before it is overwritten
    }

    // ---- Finalize: normalize and write out ----
    float inv0 = 1.f / l0;
    float inv1 = 1.f / l1;
    float* gO = out + ((size_t)b * SEQ + q0 + wrow) * HD;
    #pragma unroll
    for (int n = 0; n < 16; n++) {
        *reinterpret_cast<float2*>(&gO[g * HD + n * 8 + 2 * t]) =
            make_float2(oAcc[n][0] * inv0, oAcc[n][1] * inv0);
        *reinterpret_cast<float2*>(&gO[(g + 8) * HD + n * 8 + 2 * t]) =
            make_float2(oAcc[n][2] * inv1, oAcc[n][3] * inv1);
    }
}

extern "C" void kernel_launch(void* const* d_in, const int* in_sizes, int n_in,
                              void* d_out, int out_size) {
    const float* q  = (const float*)d_in[0];
    const float* k  = (const float*)d_in[1];
    const float* v  = (const float*)d_in[2];
    const int*   vl = (const int*)d_in[3];
    float* out = (float*)d_out;

    size_t smem_bytes = (size_t)SMEM_FLOATS * sizeof(float);   // 231424
    cudaFuncSetAttribute(fa_tf32_kernel, cudaFuncAttributeMaxDynamicSharedMemorySize, (int)smem_bytes);

    dim3 grid(SEQ / BQ, 16);  // (16, 16)
    fa_tf32_kernel<<<grid, 256, smem_bytes>>>(q, k, v, vl, out);
}